// round 12
// baseline (speedup 1.0000x reference)
#include <cuda_runtime.h>
#include <math.h>

// ------------------------------------------------------------------
// Static scratch (device globals: the sanctioned no-alloc workaround)
// ------------------------------------------------------------------
__device__ float g_ln[4096ull * 1024];          // layernorm output
__device__ float g_q [4096ull * 1024];
__device__ float g_k [4096ull * 1024];
__device__ float g_v [4096ull * 1024];
__device__ float g_o [4096ull * 1024];          // attention output (pre-proj)
__device__ float g_h1[4096ull * 2048];          // FFN hidden
__device__ float g_sc[64ull * 1024 * 1024];     // scores [B*H, S, S] = 256 MB

// ------------------------------------------------------------------
// tf32 helpers
// ------------------------------------------------------------------
__device__ __forceinline__ unsigned f2tf(float f) {
    unsigned u;
    asm("cvt.rna.tf32.f32 %0, %1;" : "=r"(u) : "f"(f));
    return u;
}
__device__ __forceinline__ void mma8(float* c, const unsigned* a, const unsigned* b) {
    asm volatile(
        "mma.sync.aligned.m16n8k8.row.col.f32.tf32.tf32.f32 "
        "{%0,%1,%2,%3}, {%4,%5,%6,%7}, {%8,%9}, {%0,%1,%2,%3};"
        : "+f"(c[0]), "+f"(c[1]), "+f"(c[2]), "+f"(c[3])
        : "r"(a[0]), "r"(a[1]), "r"(a[2]), "r"(a[3]), "r"(b[0]), "r"(b[1]));
}

// ------------------------------------------------------------------
// Block reductions (blockDim.x == 256)
// ------------------------------------------------------------------
__device__ __forceinline__ float block_sum(float v) {
    __shared__ float red[8];
    #pragma unroll
    for (int o = 16; o > 0; o >>= 1) v += __shfl_xor_sync(0xffffffffu, v, o);
    __syncthreads();
    if ((threadIdx.x & 31) == 0) red[threadIdx.x >> 5] = v;
    __syncthreads();
    float s = 0.f;
    #pragma unroll
    for (int i = 0; i < 8; i++) s += red[i];
    return s;
}
__device__ __forceinline__ float block_max(float v) {
    __shared__ float redm[8];
    #pragma unroll
    for (int o = 16; o > 0; o >>= 1) v = fmaxf(v, __shfl_xor_sync(0xffffffffu, v, o));
    __syncthreads();
    if ((threadIdx.x & 31) == 0) redm[threadIdx.x >> 5] = v;
    __syncthreads();
    float s = -3.4e38f;
    #pragma unroll
    for (int i = 0; i < 8; i++) s = fmaxf(s, redm[i]);
    return s;
}

// ------------------------------------------------------------------
// LayerNorm: 1 block per row, D=1024 (ddof=1 std, divide by std+eps)
// ------------------------------------------------------------------
__global__ void __launch_bounds__(256) ln_kernel(
    const float* __restrict__ x, const float* __restrict__ g,
    const float* __restrict__ b, float* __restrict__ y)
{
    const size_t row = blockIdx.x;
    const int t = threadIdx.x;
    float4 v = ((const float4*)(x + row * 1024))[t];
    float s = block_sum(v.x + v.y + v.z + v.w);
    float mean = s * (1.0f / 1024.0f);
    float d0 = v.x - mean, d1 = v.y - mean, d2 = v.z - mean, d3 = v.w - mean;
    float ss = block_sum(d0 * d0 + d1 * d1 + d2 * d2 + d3 * d3);
    float inv = 1.0f / (sqrtf(ss * (1.0f / 1023.0f)) + 1e-6f);
    float4 gg = ((const float4*)g)[t];
    float4 bb = ((const float4*)b)[t];
    float4 o;
    o.x = gg.x * d0 * inv + bb.x;
    o.y = gg.y * d1 * inv + bb.y;
    o.z = gg.z * d2 * inv + bb.z;
    o.w = gg.w * d3 * inv + bb.w;
    ((float4*)(y + row * 1024))[t] = o;
}

// ------------------------------------------------------------------
// Masked softmax over rows of the score buffer.
// ------------------------------------------------------------------
__global__ void __launch_bounds__(256) softmax_kernel(
    float* __restrict__ S, const int* __restrict__ mask)
{
    const size_t row = blockIdx.x;
    const int t = threadIdx.x;
    const size_t q = row & 1023;
    const size_t b = row >> 14;   // 16 heads * 1024 q per batch
    float4 v = ((const float4*)(S + row * 1024))[t];
    int4 m = ((const int4*)(mask + (b * 1024 + q) * 1024))[t];
    if (m.x == 0) v.x = -1e9f;
    if (m.y == 0) v.y = -1e9f;
    if (m.z == 0) v.z = -1e9f;
    if (m.w == 0) v.w = -1e9f;
    float mx = block_max(fmaxf(fmaxf(v.x, v.y), fmaxf(v.z, v.w)));
    v.x = __expf(v.x - mx);
    v.y = __expf(v.y - mx);
    v.z = __expf(v.z - mx);
    v.w = __expf(v.w - mx);
    float s = block_sum(v.x + v.y + v.z + v.w);
    float inv = 1.0f / s;
    v.x *= inv; v.y *= inv; v.z *= inv; v.w *= inv;
    ((float4*)(S + row * 1024))[t] = v;
}

// ------------------------------------------------------------------
// tf32 tensor-core GEMM core.
//   C[m][n] = alpha * sum_k A[m][k] * B(n,k)   (+bias, +relu, +residual)
// BTR=true : B is [N x K] row-major (weights / K matrix)
// BTR=false: B is [K x N] row-major (V matrix in PV)
// A smem: [BM][BK+4] k-contiguous (pitch 20 -> conflict-free frag loads)
// B smem: BTR same as A; !BTR: [BK][BN+8] (pitch%32==8 -> conflict-free)
// ------------------------------------------------------------------
template<int BM, int BN, int BK, int WM, int WN, int THREADS, bool BTR>
__device__ __forceinline__ void mma_core(
    const float* __restrict__ A, int lda,
    const float* __restrict__ B, int ldb,
    const float* __restrict__ bias,
    const float* __restrict__ R, int ldr,
    float* __restrict__ C, int ldc,
    int K, float alpha, int relu)
{
    constexpr int MI = WM / 16;
    constexpr int NJ = WN / 8;
    constexpr int WX = BN / WN;
    constexpr int AP = BK + 4;                          // 20 words pitch
    constexpr int BP = BTR ? (BK + 4) : (BN + 8);
    constexpr int BROWS = BTR ? BN : BK;
    constexpr int A4 = (BM * BK) / (4 * THREADS);
    constexpr int B4 = (BN * BK) / (4 * THREADS);
    static_assert((BM / WM) * (BN / WN) * 32 == THREADS, "warp layout");
    static_assert(A4 >= 1 && B4 >= 1, "staging counts");

    __shared__ unsigned Asm[BM * AP];
    __shared__ unsigned Bsm[BROWS * BP];

    const int tid  = threadIdx.x;
    const int warp = tid >> 5;
    const int lane = tid & 31;
    const int g = lane >> 2;
    const int t = lane & 3;
    const int wm0 = (warp / WX) * WM;
    const int wn0 = (warp % WX) * WN;
    const int m0 = blockIdx.y * BM;
    const int n0 = blockIdx.x * BN;

    // staging descriptors (coalesced float4 gmem loads along k / n)
    int am[A4], ak[A4];
    const float* Apt[A4];
    #pragma unroll
    for (int u = 0; u < A4; u++) {
        int idx = tid + THREADS * u;
        am[u] = idx / (BK / 4);
        ak[u] = (idx % (BK / 4)) * 4;
        Apt[u] = A + (size_t)(m0 + am[u]) * lda + ak[u];
    }
    int bm[B4], bk[B4];
    const float* Bpt[B4];
    #pragma unroll
    for (int u = 0; u < B4; u++) {
        int idx = tid + THREADS * u;
        if (BTR) {
            bm[u] = idx / (BK / 4);             // n row
            bk[u] = (idx % (BK / 4)) * 4;       // k
            Bpt[u] = B + (size_t)(n0 + bm[u]) * ldb + bk[u];
        } else {
            bm[u] = idx / (BN / 4);             // k row
            bk[u] = (idx % (BN / 4)) * 4;       // n
            Bpt[u] = B + (size_t)bm[u] * ldb + n0 + bk[u];
        }
    }

    float4 pa[A4], pb[B4];
    #pragma unroll
    for (int u = 0; u < A4; u++) pa[u] = *(const float4*)Apt[u];
    #pragma unroll
    for (int u = 0; u < B4; u++) pb[u] = *(const float4*)Bpt[u];

    float acc[MI][NJ][4];
    #pragma unroll
    for (int i = 0; i < MI; i++)
        #pragma unroll
        for (int j = 0; j < NJ; j++) {
            acc[i][j][0] = 0.f; acc[i][j][1] = 0.f;
            acc[i][j][2] = 0.f; acc[i][j][3] = 0.f;
        }

    for (int kt = 0; kt < K; kt += BK) {
        // stage (convert fp32 -> tf32 with round-to-nearest)
        #pragma unroll
        for (int u = 0; u < A4; u++) {
            uint4 s;
            s.x = f2tf(pa[u].x); s.y = f2tf(pa[u].y);
            s.z = f2tf(pa[u].z); s.w = f2tf(pa[u].w);
            *(uint4*)&Asm[am[u] * AP + ak[u]] = s;
        }
        #pragma unroll
        for (int u = 0; u < B4; u++) {
            uint4 s;
            s.x = f2tf(pb[u].x); s.y = f2tf(pb[u].y);
            s.z = f2tf(pb[u].z); s.w = f2tf(pb[u].w);
            *(uint4*)&Bsm[bm[u] * BP + bk[u]] = s;
        }
        __syncthreads();

        // prefetch next tile into registers
        if (kt + BK < K) {
            #pragma unroll
            for (int u = 0; u < A4; u++)
                pa[u] = *(const float4*)(Apt[u] + (kt + BK));
            #pragma unroll
            for (int u = 0; u < B4; u++) {
                if (BTR) pb[u] = *(const float4*)(Bpt[u] + (kt + BK));
                else     pb[u] = *(const float4*)(Bpt[u] + (size_t)(kt + BK) * ldb);
            }
        }

        // compute: BK/8 k-steps of m16n8k8
        #pragma unroll
        for (int ks = 0; ks < BK / 8; ks++) {
            const int k0 = ks * 8;
            unsigned af[MI][4], bf[NJ][2];
            #pragma unroll
            for (int i = 0; i < MI; i++) {
                const int m = wm0 + i * 16 + g;
                af[i][0] = Asm[m * AP + k0 + t];
                af[i][1] = Asm[(m + 8) * AP + k0 + t];
                af[i][2] = Asm[m * AP + k0 + t + 4];
                af[i][3] = Asm[(m + 8) * AP + k0 + t + 4];
            }
            #pragma unroll
            for (int j = 0; j < NJ; j++) {
                const int n = wn0 + j * 8 + g;
                if (BTR) {
                    bf[j][0] = Bsm[n * BP + k0 + t];
                    bf[j][1] = Bsm[n * BP + k0 + t + 4];
                } else {
                    bf[j][0] = Bsm[(k0 + t) * BP + n];
                    bf[j][1] = Bsm[(k0 + t + 4) * BP + n];
                }
            }
            #pragma unroll
            for (int i = 0; i < MI; i++)
                #pragma unroll
                for (int j = 0; j < NJ; j++)
                    mma8(acc[i][j], af[i], bf[j]);
        }
        __syncthreads();
    }

    // epilogue: alpha, bias, relu, residual, store float2 pairs
    #pragma unroll
    for (int i = 0; i < MI; i++) {
        #pragma unroll
        for (int j = 0; j < NJ; j++) {
            const int m = m0 + wm0 + i * 16 + g;
            const int n = n0 + wn0 + j * 8 + 2 * t;
            float v0 = acc[i][j][0] * alpha;
            float v1 = acc[i][j][1] * alpha;
            float v2 = acc[i][j][2] * alpha;
            float v3 = acc[i][j][3] * alpha;
            if (bias) {
                float b0 = bias[n], b1 = bias[n + 1];
                v0 += b0; v1 += b1; v2 += b0; v3 += b1;
            }
            if (relu) {
                v0 = fmaxf(v0, 0.f); v1 = fmaxf(v1, 0.f);
                v2 = fmaxf(v2, 0.f); v3 = fmaxf(v3, 0.f);
            }
            if (R) {
                const float* r0 = R + (size_t)m * ldr + n;
                const float* r1 = R + (size_t)(m + 8) * ldr + n;
                v0 += r0[0]; v1 += r0[1];
                v2 += r1[0]; v3 += r1[1];
            }
            float2 s0; s0.x = v0; s0.y = v1;
            float2 s1; s1.x = v2; s1.y = v3;
            *(float2*)(C + (size_t)m * ldc + n) = s0;
            *(float2*)(C + (size_t)(m + 8) * ldc + n) = s1;
        }
    }
}

// ------------------------------------------------------------------
// GEMM wrappers
// ------------------------------------------------------------------
// Projections / FFN: C[M,N] = A[M,K] @ W[N,K]^T (+bias,+relu,+residual)
__global__ void __launch_bounds__(256, 2) tgemm_nt(
    const float* __restrict__ A, const float* __restrict__ W,
    const float* __restrict__ bias, const float* __restrict__ R,
    float* __restrict__ C, int N, int K, int relu)
{
    mma_core<128, 128, 16, 64, 32, 256, true>(
        A, K, W, K, bias, R, N, C, N, K, 1.0f, relu);
}

// Batched QK^T: per z=(b*16+h): S[z] = 0.125 * Q_slice @ K_slice^T
__global__ void __launch_bounds__(256, 2) tqk(
    const float* __restrict__ Q, const float* __restrict__ Km,
    float* __restrict__ S)
{
    const int z = blockIdx.z, b = z >> 4, h = z & 15;
    const float* Aq = Q  + ((size_t)b * 1024) * 1024 + h * 64;
    const float* Bk = Km + ((size_t)b * 1024) * 1024 + h * 64;
    float* Cs = S + (size_t)z * 1024 * 1024;
    mma_core<128, 128, 16, 64, 32, 256, true>(
        Aq, 1024, Bk, 1024, (const float*)0, (const float*)0, 0,
        Cs, 1024, 64, 0.125f, 0);
}

// Batched PV: per z: O_slice = P[z] @ V_slice  (B is [K][N] row-major)
__global__ void __launch_bounds__(256, 2) tpv(
    const float* __restrict__ P, const float* __restrict__ V,
    float* __restrict__ O)
{
    const int z = blockIdx.z, b = z >> 4, h = z & 15;
    const float* Ap = P + (size_t)z * 1024 * 1024;
    const float* Bv = V + ((size_t)b * 1024) * 1024 + h * 64;
    float* Co = O + ((size_t)b * 1024) * 1024 + h * 64;
    mma_core<128, 64, 16, 32, 32, 256, false>(
        Ap, 1024, Bv, 1024, (const float*)0, (const float*)0, 0,
        Co, 1024, 1024, 1.0f, 0);
}

// ------------------------------------------------------------------
// Host orchestration (graph-capturable: launches + one async D2D copy)
// ------------------------------------------------------------------
extern "C" void kernel_launch(void* const* d_in, const int* in_sizes, int n_in,
                              void* d_out, int out_size)
{
    (void)in_sizes; (void)n_in; (void)out_size;

    const float* we   = (const float*)d_in[0];
    const int*   mask = (const int*)d_in[1];
    const float* wq = (const float*)d_in[2],  *bq = (const float*)d_in[3];
    const float* wk = (const float*)d_in[4],  *bk = (const float*)d_in[5];
    const float* wv = (const float*)d_in[6],  *bv = (const float*)d_in[7];
    const float* wo = (const float*)d_in[8],  *bo = (const float*)d_in[9];
    const float* w1 = (const float*)d_in[10], *b1 = (const float*)d_in[11];
    const float* w2 = (const float*)d_in[12], *b2 = (const float*)d_in[13];
    const float* ln1a = (const float*)d_in[14], *ln1b = (const float*)d_in[15];
    const float* ln2a = (const float*)d_in[16], *ln2b = (const float*)d_in[17];
    const float* lnfa = (const float*)d_in[18], *lnfb = (const float*)d_in[19];

    float* x = (float*)d_out;   // residual stream lives in d_out

    float *ln, *q, *k, *v, *o, *h1, *sc;
    cudaGetSymbolAddress((void**)&ln, g_ln);
    cudaGetSymbolAddress((void**)&q,  g_q);
    cudaGetSymbolAddress((void**)&k,  g_k);
    cudaGetSymbolAddress((void**)&v,  g_v);
    cudaGetSymbolAddress((void**)&o,  g_o);
    cudaGetSymbolAddress((void**)&h1, g_h1);
    cudaGetSymbolAddress((void**)&sc, g_sc);

    cudaMemcpyAsync(x, we, sizeof(float) * 4096ull * 1024,
                    cudaMemcpyDeviceToDevice, 0);

    const dim3 thr(256);
    for (int L = 0; L < 6; ++L) {
        const size_t odd = (size_t)L * 1024 * 1024;   // d*d weights
        const size_t od  = (size_t)L * 1024;          // d vectors
        const size_t off = (size_t)L * 2048 * 1024;   // f*d weights
        const size_t of  = (size_t)L * 2048;          // f vectors

        // x -> ln1(x)
        ln_kernel<<<4096, thr>>>(x, ln1a + od, ln1b + od, ln);
        // Q/K/V projections
        tgemm_nt<<<dim3(8, 32), thr>>>(ln, wq + odd, bq + od, (const float*)0, q, 1024, 1024, 0);
        tgemm_nt<<<dim3(8, 32), thr>>>(ln, wk + odd, bk + od, (const float*)0, k, 1024, 1024, 0);
        tgemm_nt<<<dim3(8, 32), thr>>>(ln, wv + odd, bv + od, (const float*)0, v, 1024, 1024, 0);
        // attention
        tqk<<<dim3(8, 8, 64), thr>>>(q, k, sc);
        softmax_kernel<<<65536, thr>>>(sc, mask);
        tpv<<<dim3(1, 8, 64), thr>>>(sc, v, o);
        // output projection + residual add (fused)
        tgemm_nt<<<dim3(8, 32), thr>>>(o, wo + odd, bo + od, x, x, 1024, 1024, 0);
        // FFN sublayer
        ln_kernel<<<4096, thr>>>(x, ln2a + od, ln2b + od, ln);
        tgemm_nt<<<dim3(16, 32), thr>>>(ln, w1 + off, b1 + of, (const float*)0, h1, 2048, 1024, 1);
        tgemm_nt<<<dim3(8, 32), thr>>>(h1, w2 + off, b2 + od, x, x, 1024, 2048, 0);
    }
    // final layernorm (in-place safe: row read into regs before write)
    ln_kernel<<<4096, thr>>>(x, lnfa, lnfb, x);
}

// round 13
// speedup vs baseline: 1.2917x; 1.2917x over previous
#include <cuda_runtime.h>
#include <math.h>

// ------------------------------------------------------------------
// Static scratch (device globals: the sanctioned no-alloc workaround)
// ------------------------------------------------------------------
__device__ float g_ln[4096ull * 1024];          // layernorm output (tf32-rounded)
__device__ float g_q [4096ull * 1024];
__device__ float g_k [4096ull * 1024];
__device__ float g_v [4096ull * 1024];
__device__ float g_o [4096ull * 1024];          // attention output (pre-proj)
__device__ float g_h1[4096ull * 2048];          // FFN hidden
__device__ float g_sc[64ull * 1024 * 1024];     // scores [B*H, S, S] = 256 MB
__device__ float g_wt[50331648ull];             // tf32-rounded weights (192 MB)

// ------------------------------------------------------------------
// tf32 helpers
// ------------------------------------------------------------------
__device__ __forceinline__ unsigned f2tf(float f) {
    unsigned u;
    asm("cvt.rna.tf32.f32 %0, %1;" : "=r"(u) : "f"(f));
    return u;
}
__device__ __forceinline__ float rtf(float f) { return __uint_as_float(f2tf(f)); }

__device__ __forceinline__ void mma8(float* c, const unsigned* a, const unsigned* b) {
    asm volatile(
        "mma.sync.aligned.m16n8k8.row.col.f32.tf32.tf32.f32 "
        "{%0,%1,%2,%3}, {%4,%5,%6,%7}, {%8,%9}, {%0,%1,%2,%3};"
        : "+f"(c[0]), "+f"(c[1]), "+f"(c[2]), "+f"(c[3])
        : "r"(a[0]), "r"(a[1]), "r"(a[2]), "r"(a[3]), "r"(b[0]), "r"(b[1]));
}

// cp.async 16B gmem -> smem
__device__ __forceinline__ void cp16(unsigned* dst, const float* src) {
    unsigned d = (unsigned)__cvta_generic_to_shared(dst);
    asm volatile("cp.async.cg.shared.global [%0], [%1], 16;" :: "r"(d), "l"(src));
}
#define CP_COMMIT() asm volatile("cp.async.commit_group;")

// ------------------------------------------------------------------
// Weight tf32 pre-rounding (once per launch; elementwise)
// ------------------------------------------------------------------
__global__ void __launch_bounds__(256) conv_tf32(
    const float4* __restrict__ in, float4* __restrict__ out, int n4)
{
    int i = blockIdx.x * blockDim.x + threadIdx.x;
    if (i < n4) {
        float4 v = in[i];
        v.x = rtf(v.x); v.y = rtf(v.y); v.z = rtf(v.z); v.w = rtf(v.w);
        out[i] = v;
    }
}

// ------------------------------------------------------------------
// Block reductions (blockDim.x == 256)
// ------------------------------------------------------------------
__device__ __forceinline__ float block_sum(float v) {
    __shared__ float red[8];
    #pragma unroll
    for (int o = 16; o > 0; o >>= 1) v += __shfl_xor_sync(0xffffffffu, v, o);
    __syncthreads();
    if ((threadIdx.x & 31) == 0) red[threadIdx.x >> 5] = v;
    __syncthreads();
    float s = 0.f;
    #pragma unroll
    for (int i = 0; i < 8; i++) s += red[i];
    return s;
}
__device__ __forceinline__ float block_max(float v) {
    __shared__ float redm[8];
    #pragma unroll
    for (int o = 16; o > 0; o >>= 1) v = fmaxf(v, __shfl_xor_sync(0xffffffffu, v, o));
    __syncthreads();
    if ((threadIdx.x & 31) == 0) redm[threadIdx.x >> 5] = v;
    __syncthreads();
    float s = -3.4e38f;
    #pragma unroll
    for (int i = 0; i < 8; i++) s = fmaxf(s, redm[i]);
    return s;
}

// ------------------------------------------------------------------
// LayerNorm: 1 block per row, D=1024 (ddof=1 std, divide by std+eps)
// rnd!=0 -> round output to tf32 (it feeds a GEMM A-operand)
// ------------------------------------------------------------------
__global__ void __launch_bounds__(256) ln_kernel(
    const float* __restrict__ x, const float* __restrict__ g,
    const float* __restrict__ b, float* __restrict__ y, int rnd)
{
    const size_t row = blockIdx.x;
    const int t = threadIdx.x;
    float4 v = ((const float4*)(x + row * 1024))[t];
    float s = block_sum(v.x + v.y + v.z + v.w);
    float mean = s * (1.0f / 1024.0f);
    float d0 = v.x - mean, d1 = v.y - mean, d2 = v.z - mean, d3 = v.w - mean;
    float ss = block_sum(d0 * d0 + d1 * d1 + d2 * d2 + d3 * d3);
    float inv = 1.0f / (sqrtf(ss * (1.0f / 1023.0f)) + 1e-6f);
    float4 gg = ((const float4*)g)[t];
    float4 bb = ((const float4*)b)[t];
    float4 o;
    o.x = gg.x * d0 * inv + bb.x;
    o.y = gg.y * d1 * inv + bb.y;
    o.z = gg.z * d2 * inv + bb.z;
    o.w = gg.w * d3 * inv + bb.w;
    if (rnd) { o.x = rtf(o.x); o.y = rtf(o.y); o.z = rtf(o.z); o.w = rtf(o.w); }
    ((float4*)(y + row * 1024))[t] = o;
}

// ------------------------------------------------------------------
// Masked softmax; output rounded to tf32 (feeds PV A-operand)
// ------------------------------------------------------------------
__global__ void __launch_bounds__(256) softmax_kernel(
    float* __restrict__ S, const int* __restrict__ mask)
{
    const size_t row = blockIdx.x;
    const int t = threadIdx.x;
    const size_t q = row & 1023;
    const size_t b = row >> 14;   // 16 heads * 1024 q per batch
    float4 v = ((const float4*)(S + row * 1024))[t];
    int4 m = ((const int4*)(mask + (b * 1024 + q) * 1024))[t];
    if (m.x == 0) v.x = -1e9f;
    if (m.y == 0) v.y = -1e9f;
    if (m.z == 0) v.z = -1e9f;
    if (m.w == 0) v.w = -1e9f;
    float mx = block_max(fmaxf(fmaxf(v.x, v.y), fmaxf(v.z, v.w)));
    v.x = __expf(v.x - mx);
    v.y = __expf(v.y - mx);
    v.z = __expf(v.z - mx);
    v.w = __expf(v.w - mx);
    float s = block_sum(v.x + v.y + v.z + v.w);
    float inv = 1.0f / s;
    v.x = rtf(v.x * inv); v.y = rtf(v.y * inv);
    v.z = rtf(v.z * inv); v.w = rtf(v.w * inv);
    ((float4*)(S + row * 1024))[t] = v;
}

// ------------------------------------------------------------------
// Pipelined tf32 tensor-core GEMM (cp.async double-buffered).
// Inputs MUST be pre-rounded tf32-in-fp32 (no conversion in kernel).
//   C = alpha * A[M,K] @ B[N,K]^T (+bias, +relu, +residual, +round)
// 128 threads, warps 2x2 of 64x64, BM=BN=128, BK=32.
// smem pitch BK+4=36 -> conflict-free fragment loads (4g+t distinct mod 32).
// ------------------------------------------------------------------
template<int BM, int BN, int BK, int WM, int WN, int THREADS>
__device__ __forceinline__ void mma_pipe(
    const float* __restrict__ A, int lda,
    const float* __restrict__ B, int ldb,
    const float* __restrict__ bias,
    const float* __restrict__ R, int ldr,
    float* __restrict__ C, int ldc,
    int K, float alpha, int relu, int rnd)
{
    constexpr int MI = WM / 16;
    constexpr int NJ = WN / 8;
    constexpr int WX = BN / WN;
    constexpr int AP = BK + 4;
    constexpr int BP = BK + 4;
    constexpr int AW = BM * AP;                  // words per A stage
    constexpr int BW = BN * BP;
    constexpr int A4 = (BM * BK) / (4 * THREADS);
    constexpr int B4 = (BN * BK) / (4 * THREADS);
    constexpr int CH = BK / 4;                   // 16B chunks per row
    constexpr int RSTEP = THREADS / CH;          // rows advanced per unroll step
    static_assert((BM / WM) * (BN / WN) * 32 == THREADS, "warp layout");

    extern __shared__ unsigned sm[];

    const int tid  = threadIdx.x;
    const int warp = tid >> 5;
    const int lane = tid & 31;
    const int g = lane >> 2;
    const int t = lane & 3;
    const int wm0 = (warp / WX) * WM;
    const int wn0 = (warp % WX) * WN;
    const int m0 = blockIdx.y * BM;
    const int n0 = blockIdx.x * BN;

    // staging geometry: row = tid/CH (+RSTEP per step), chunk col = (tid%CH)*4
    const int r0 = tid / CH;
    const int c0 = (tid % CH) * 4;
    const float* Ag = A + (size_t)(m0 + r0) * lda + c0;
    const float* Bg = B + (size_t)(n0 + r0) * ldb + c0;
    unsigned* Asd = &sm[r0 * AP + c0];
    unsigned* Bsd = &sm[AW + r0 * BP + c0];

    const int nIter = K / BK;

    // stage 0
    #pragma unroll
    for (int u = 0; u < A4; u++) cp16(Asd + u * RSTEP * AP, Ag + (size_t)u * RSTEP * lda);
    #pragma unroll
    for (int u = 0; u < B4; u++) cp16(Bsd + u * RSTEP * BP, Bg + (size_t)u * RSTEP * ldb);
    CP_COMMIT();

    float acc[MI][NJ][4];
    #pragma unroll
    for (int i = 0; i < MI; i++)
        #pragma unroll
        for (int j = 0; j < NJ; j++) {
            acc[i][j][0] = 0.f; acc[i][j][1] = 0.f;
            acc[i][j][2] = 0.f; acc[i][j][3] = 0.f;
        }

    for (int it = 0; it < nIter; it++) {
        const int cur = (it & 1) * (AW + BW);
        if (it + 1 < nIter) {
            const int nxt = ((it + 1) & 1) * (AW + BW);
            const int kt = (it + 1) * BK;
            #pragma unroll
            for (int u = 0; u < A4; u++)
                cp16(Asd + nxt + u * RSTEP * AP, Ag + kt + (size_t)u * RSTEP * lda);
            #pragma unroll
            for (int u = 0; u < B4; u++)
                cp16(Bsd + nxt + u * RSTEP * BP, Bg + kt + (size_t)u * RSTEP * ldb);
            CP_COMMIT();
            asm volatile("cp.async.wait_group 1;");
        } else {
            asm volatile("cp.async.wait_group 0;");
        }
        __syncthreads();

        const unsigned* Asm = &sm[cur];
        const unsigned* Bsm = &sm[cur + AW];

        #pragma unroll
        for (int ks = 0; ks < BK / 8; ks++) {
            const int k0 = ks * 8;
            unsigned af[MI][4], bf[NJ][2];
            #pragma unroll
            for (int i = 0; i < MI; i++) {
                const int m = wm0 + i * 16 + g;
                af[i][0] = Asm[m * AP + k0 + t];
                af[i][1] = Asm[(m + 8) * AP + k0 + t];
                af[i][2] = Asm[m * AP + k0 + t + 4];
                af[i][3] = Asm[(m + 8) * AP + k0 + t + 4];
            }
            #pragma unroll
            for (int j = 0; j < NJ; j++) {
                const int n = wn0 + j * 8 + g;
                bf[j][0] = Bsm[n * BP + k0 + t];
                bf[j][1] = Bsm[n * BP + k0 + t + 4];
            }
            #pragma unroll
            for (int i = 0; i < MI; i++)
                #pragma unroll
                for (int j = 0; j < NJ; j++)
                    mma8(acc[i][j], af[i], bf[j]);
        }
        __syncthreads();
    }

    // epilogue: alpha, bias, relu, residual, optional tf32 rounding
    #pragma unroll
    for (int i = 0; i < MI; i++) {
        #pragma unroll
        for (int j = 0; j < NJ; j++) {
            const int m = m0 + wm0 + i * 16 + g;
            const int n = n0 + wn0 + j * 8 + 2 * t;
            float v0 = acc[i][j][0] * alpha;
            float v1 = acc[i][j][1] * alpha;
            float v2 = acc[i][j][2] * alpha;
            float v3 = acc[i][j][3] * alpha;
            if (bias) {
                float b0 = bias[n], b1 = bias[n + 1];
                v0 += b0; v1 += b1; v2 += b0; v3 += b1;
            }
            if (relu) {
                v0 = fmaxf(v0, 0.f); v1 = fmaxf(v1, 0.f);
                v2 = fmaxf(v2, 0.f); v3 = fmaxf(v3, 0.f);
            }
            if (R) {
                const float* r0p = R + (size_t)m * ldr + n;
                const float* r1p = R + (size_t)(m + 8) * ldr + n;
                v0 += r0p[0]; v1 += r0p[1];
                v2 += r1p[0]; v3 += r1p[1];
            }
            if (rnd) { v0 = rtf(v0); v1 = rtf(v1); v2 = rtf(v2); v3 = rtf(v3); }
            float2 s0; s0.x = v0; s0.y = v1;
            float2 s1; s1.x = v2; s1.y = v3;
            *(float2*)(C + (size_t)m * ldc + n) = s0;
            *(float2*)(C + (size_t)(m + 8) * ldc + n) = s1;
        }
    }
}

constexpr int PIPE_SMEM = 2 * (128 * 36 + 128 * 36) * 4;  // 73728 bytes

// Projections / FFN: C[M,N] = A[M,K] @ W[N,K]^T
__global__ void __launch_bounds__(128, 2) tg_pipe(
    const float* __restrict__ A, const float* __restrict__ W,
    const float* __restrict__ bias, const float* __restrict__ R,
    float* __restrict__ C, int N, int K, int relu, int rnd)
{
    mma_pipe<128, 128, 32, 64, 64, 128>(A, K, W, K, bias, R, N, C, N, K, 1.0f, relu, rnd);
}

// Batched QK^T: per z=(b*16+h): S[z] = 0.125 * Q_slice @ K_slice^T
__global__ void __launch_bounds__(128, 2) tqk_pipe(
    const float* __restrict__ Q, const float* __restrict__ Km,
    float* __restrict__ S)
{
    const int z = blockIdx.z, b = z >> 4, h = z & 15;
    const float* Aq = Q  + ((size_t)b << 20) + h * 64;
    const float* Bk = Km + ((size_t)b << 20) + h * 64;
    float* Cs = S + ((size_t)z << 20);
    mma_pipe<128, 128, 32, 64, 64, 128>(Aq, 1024, Bk, 1024,
                                        (const float*)0, (const float*)0, 0,
                                        Cs, 1024, 64, 0.125f, 0, 0);
}

// ------------------------------------------------------------------
// PV GEMM (old register-prefetch core; B is [K][N] row-major, N=64).
// Inputs pre-rounded; output rounded (feeds o-projection).
// ------------------------------------------------------------------
template<int BM, int BN, int BK, int WM, int WN, int THREADS>
__device__ __forceinline__ void mma_pv_core(
    const float* __restrict__ A, int lda,
    const float* __restrict__ B, int ldb,
    float* __restrict__ C, int ldc, int K)
{
    constexpr int MI = WM / 16;
    constexpr int NJ = WN / 8;
    constexpr int WX = BN / WN;
    constexpr int AP = BK + 4;
    constexpr int BP = BN + 8;
    constexpr int A4 = (BM * BK) / (4 * THREADS);
    constexpr int B4 = (BN * BK) / (4 * THREADS);

    __shared__ unsigned Asm[BM * AP];
    __shared__ unsigned Bsm[BK * BP];

    const int tid  = threadIdx.x;
    const int warp = tid >> 5;
    const int lane = tid & 31;
    const int g = lane >> 2;
    const int t = lane & 3;
    const int wm0 = (warp / WX) * WM;
    const int wn0 = (warp % WX) * WN;
    const int m0 = blockIdx.y * BM;
    const int n0 = blockIdx.x * BN;

    int am[A4], ak[A4];
    const float* Apt[A4];
    #pragma unroll
    for (int u = 0; u < A4; u++) {
        int idx = tid + THREADS * u;
        am[u] = idx / (BK / 4);
        ak[u] = (idx % (BK / 4)) * 4;
        Apt[u] = A + (size_t)(m0 + am[u]) * lda + ak[u];
    }
    int bm[B4], bk[B4];
    const float* Bpt[B4];
    #pragma unroll
    for (int u = 0; u < B4; u++) {
        int idx = tid + THREADS * u;
        bm[u] = idx / (BN / 4);
        bk[u] = (idx % (BN / 4)) * 4;
        Bpt[u] = B + (size_t)bm[u] * ldb + n0 + bk[u];
    }

    float4 pa[A4], pb[B4];
    #pragma unroll
    for (int u = 0; u < A4; u++) pa[u] = *(const float4*)Apt[u];
    #pragma unroll
    for (int u = 0; u < B4; u++) pb[u] = *(const float4*)Bpt[u];

    float acc[MI][NJ][4];
    #pragma unroll
    for (int i = 0; i < MI; i++)
        #pragma unroll
        for (int j = 0; j < NJ; j++) {
            acc[i][j][0] = 0.f; acc[i][j][1] = 0.f;
            acc[i][j][2] = 0.f; acc[i][j][3] = 0.f;
        }

    for (int kt = 0; kt < K; kt += BK) {
        #pragma unroll
        for (int u = 0; u < A4; u++)
            *(uint4*)&Asm[am[u] * AP + ak[u]] = *(const uint4*)&pa[u];
        #pragma unroll
        for (int u = 0; u < B4; u++)
            *(uint4*)&Bsm[bm[u] * BP + bk[u]] = *(const uint4*)&pb[u];
        __syncthreads();

        if (kt + BK < K) {
            #pragma unroll
            for (int u = 0; u < A4; u++)
                pa[u] = *(const float4*)(Apt[u] + (kt + BK));
            #pragma unroll
            for (int u = 0; u < B4; u++)
                pb[u] = *(const float4*)(Bpt[u] + (size_t)(kt + BK) * ldb);
        }

        #pragma unroll
        for (int ks = 0; ks < BK / 8; ks++) {
            const int k0 = ks * 8;
            unsigned af[MI][4], bf[NJ][2];
            #pragma unroll
            for (int i = 0; i < MI; i++) {
                const int m = wm0 + i * 16 + g;
                af[i][0] = Asm[m * AP + k0 + t];
                af[i][1] = Asm[(m + 8) * AP + k0 + t];
                af[i][2] = Asm[m * AP + k0 + t + 4];
                af[i][3] = Asm[(m + 8) * AP + k0 + t + 4];
            }
            #pragma unroll
            for (int j = 0; j < NJ; j++) {
                const int n = wn0 + j * 8 + g;
                bf[j][0] = Bsm[(k0 + t) * BP + n];
                bf[j][1] = Bsm[(k0 + t + 4) * BP + n];
            }
            #pragma unroll
            for (int i = 0; i < MI; i++)
                #pragma unroll
                for (int j = 0; j < NJ; j++)
                    mma8(acc[i][j], af[i], bf[j]);
        }
        __syncthreads();
    }

    #pragma unroll
    for (int i = 0; i < MI; i++) {
        #pragma unroll
        for (int j = 0; j < NJ; j++) {
            const int m = m0 + wm0 + i * 16 + g;
            const int n = n0 + wn0 + j * 8 + 2 * t;
            float2 s0, s1;
            s0.x = rtf(acc[i][j][0]); s0.y = rtf(acc[i][j][1]);
            s1.x = rtf(acc[i][j][2]); s1.y = rtf(acc[i][j][3]);
            *(float2*)(C + (size_t)m * ldc + n) = s0;
            *(float2*)(C + (size_t)(m + 8) * ldc + n) = s1;
        }
    }
}

__global__ void __launch_bounds__(256, 2) tpv(
    const float* __restrict__ P, const float* __restrict__ V,
    float* __restrict__ O)
{
    const int z = blockIdx.z, b = z >> 4, h = z & 15;
    const float* Ap = P + ((size_t)z << 20);
    const float* Bv = V + ((size_t)b << 20) + h * 64;
    float* Co = O + ((size_t)b << 20) + h * 64;
    mma_pv_core<128, 64, 16, 32, 32, 256>(Ap, 1024, Bv, 1024, Co, 1024, 1024);
}

// ------------------------------------------------------------------
// Host orchestration (graph-capturable: launches + one async D2D copy)
// ------------------------------------------------------------------
extern "C" void kernel_launch(void* const* d_in, const int* in_sizes, int n_in,
                              void* d_out, int out_size)
{
    (void)in_sizes; (void)n_in; (void)out_size;

    const float* we   = (const float*)d_in[0];
    const int*   mask = (const int*)d_in[1];
    const float* wq = (const float*)d_in[2],  *bq = (const float*)d_in[3];
    const float* wk = (const float*)d_in[4],  *bk = (const float*)d_in[5];
    const float* wv = (const float*)d_in[6],  *bv = (const float*)d_in[7];
    const float* wo = (const float*)d_in[8],  *bo = (const float*)d_in[9];
    const float* w1 = (const float*)d_in[10], *b1 = (const float*)d_in[11];
    const float* w2 = (const float*)d_in[12], *b2 = (const float*)d_in[13];
    const float* ln1a = (const float*)d_in[14], *ln1b = (const float*)d_in[15];
    const float* ln2a = (const float*)d_in[16], *ln2b = (const float*)d_in[17];
    const float* lnfa = (const float*)d_in[18], *lnfb = (const float*)d_in[19];

    float* x = (float*)d_out;   // residual stream lives in d_out

    float *ln, *q, *k, *v, *o, *h1, *sc, *wt;
    cudaGetSymbolAddress((void**)&ln, g_ln);
    cudaGetSymbolAddress((void**)&q,  g_q);
    cudaGetSymbolAddress((void**)&k,  g_k);
    cudaGetSymbolAddress((void**)&v,  g_v);
    cudaGetSymbolAddress((void**)&o,  g_o);
    cudaGetSymbolAddress((void**)&h1, g_h1);
    cudaGetSymbolAddress((void**)&sc, g_sc);
    cudaGetSymbolAddress((void**)&wt, g_wt);

    // tf32-rounded weight mirrors
    const size_t NQKV = 6ull * 1024 * 1024;   // 6 layers * d*d
    const size_t NFF  = 6ull * 2048 * 1024;   // 6 layers * f*d
    float* wq_t = wt;
    float* wk_t = wq_t + NQKV;
    float* wv_t = wk_t + NQKV;
    float* wo_t = wv_t + NQKV;
    float* w1_t = wo_t + NQKV;
    float* w2_t = w1_t + NFF;

    static bool attr_done = false;
    if (!attr_done) {
        cudaFuncSetAttribute(tg_pipe,  cudaFuncAttributeMaxDynamicSharedMemorySize, PIPE_SMEM);
        cudaFuncSetAttribute(tqk_pipe, cudaFuncAttributeMaxDynamicSharedMemorySize, PIPE_SMEM);
        attr_done = true;
    }

    cudaMemcpyAsync(x, we, sizeof(float) * 4096ull * 1024,
                    cudaMemcpyDeviceToDevice, 0);

    // pre-round all weights to tf32 (once per launch)
    conv_tf32<<<(int)(NQKV / 1024), 256>>>((const float4*)wq, (float4*)wq_t, (int)(NQKV / 4));
    conv_tf32<<<(int)(NQKV / 1024), 256>>>((const float4*)wk, (float4*)wk_t, (int)(NQKV / 4));
    conv_tf32<<<(int)(NQKV / 1024), 256>>>((const float4*)wv, (float4*)wv_t, (int)(NQKV / 4));
    conv_tf32<<<(int)(NQKV / 1024), 256>>>((const float4*)wo, (float4*)wo_t, (int)(NQKV / 4));
    conv_tf32<<<(int)(NFF  / 1024), 256>>>((const float4*)w1, (float4*)w1_t, (int)(NFF / 4));
    conv_tf32<<<(int)(NFF  / 1024), 256>>>((const float4*)w2, (float4*)w2_t, (int)(NFF / 4));

    const dim3 t128(128), t256(256);
    for (int L = 0; L < 6; ++L) {
        const size_t odd = (size_t)L * 1024 * 1024;   // d*d weights
        const size_t od  = (size_t)L * 1024;          // d vectors
        const size_t off = (size_t)L * 2048 * 1024;   // f*d weights
        const size_t of  = (size_t)L * 2048;          // f vectors

        // x -> ln1(x), tf32-rounded
        ln_kernel<<<4096, t256>>>(x, ln1a + od, ln1b + od, ln, 1);
        // Q/K/V projections (outputs rounded: feed attention GEMMs)
        tg_pipe<<<dim3(8, 32), t128, PIPE_SMEM>>>(ln, wq_t + odd, bq + od, (const float*)0, q, 1024, 1024, 0, 1);
        tg_pipe<<<dim3(8, 32), t128, PIPE_SMEM>>>(ln, wk_t + odd, bk + od, (const float*)0, k, 1024, 1024, 0, 1);
        tg_pipe<<<dim3(8, 32), t128, PIPE_SMEM>>>(ln, wv_t + odd, bv + od, (const float*)0, v, 1024, 1024, 0, 1);
        // attention
        tqk_pipe<<<dim3(8, 8, 64), t128, PIPE_SMEM>>>(q, k, sc);
        softmax_kernel<<<65536, t256>>>(sc, mask);
        tpv<<<dim3(1, 8, 64), t256>>>(sc, v, o);
        // output projection + residual (full fp32 output into x)
        tg_pipe<<<dim3(8, 32), t128, PIPE_SMEM>>>(o, wo_t + odd, bo + od, x, x, 1024, 1024, 0, 0);
        // FFN sublayer
        ln_kernel<<<4096, t256>>>(x, ln2a + od, ln2b + od, ln, 1);
        tg_pipe<<<dim3(16, 32), t128, PIPE_SMEM>>>(ln, w1_t + off, b1 + of, (const float*)0, h1, 2048, 1024, 1, 1);
        tg_pipe<<<dim3(8, 32), t128, PIPE_SMEM>>>(h1, w2_t + off, b2 + od, x, x, 1024, 2048, 0, 0);
    }
    // final layernorm (no rounding; output is the result)
    ln_kernel<<<4096, t256>>>(x, lnfa, lnfb, x, 0);
}